// round 17
// baseline (speedup 1.0000x reference)
#include <cuda_runtime.h>
#include <stdint.h>
#include <math.h>

#define B_ 4
#define N_ 4096
#define D_ 256
#define K_ 32
#define NC 40
#define INV_T 14.285714285714285714f

__device__ float g_f1n[(size_t)B_ * N_ * D_];
__device__ float g_f2n[(size_t)B_ * N_ * D_];
__device__ float g_cv[(size_t)B_ * N_ * NC];
__device__ int   g_ci[(size_t)B_ * N_ * NC];

// ---------------------------------------------------------------------------
__device__ __forceinline__ unsigned long long ffma2(unsigned long long a,
                                                    unsigned long long b,
                                                    unsigned long long c) {
    unsigned long long d;
    asm("fma.rn.f32x2 %0, %1, %2, %3;" : "=l"(d) : "l"(a), "l"(b), "l"(c));
    return d;
}

// ---------------------------------------------------------------------------
// K1: normalize (fp32 division, like jax)
// ---------------------------------------------------------------------------
__global__ void normalize_kernel(const float* __restrict__ F1,
                                 const float* __restrict__ F2) {
    int gw = (blockIdx.x * blockDim.x + threadIdx.x) >> 5;
    int lane = threadIdx.x & 31;
    const int R = B_ * N_;
    if (gw >= 2 * R) return;

    const float* src;
    float* fdst;
    int row;
    if (gw < R) { src = F1; fdst = g_f1n; row = gw; }
    else        { src = F2; fdst = g_f2n; row = gw - R; }

    const float4* s4 = (const float4*)(src + (size_t)row * D_);
    float4 v0 = s4[lane];
    float4 v1 = s4[lane + 32];
    float ss = v0.x*v0.x + v0.y*v0.y + v0.z*v0.z + v0.w*v0.w
             + v1.x*v1.x + v1.y*v1.y + v1.z*v1.z + v1.w*v1.w;
#pragma unroll
    for (int o = 16; o; o >>= 1) ss += __shfl_xor_sync(0xffffffffu, ss, o);
    float nrm = fmaxf(sqrtf(ss), 1e-12f);

    float4* o4 = (float4*)(fdst + (size_t)row * D_);
    o4[lane]      = make_float4(v0.x/nrm, v0.y/nrm, v0.z/nrm, v0.w/nrm);
    o4[lane + 32] = make_float4(v1.x/nrm, v1.y/nrm, v1.z/nrm, v1.w/nrm);
}

// ---------------------------------------------------------------------------
// K2: high-occupancy FFMA2 SGEMM, sim -> out[0 .. B*N*N)
// CTA 128x128, 256 thr, 8x8 thread tile, K chunks of 16, double buffer
// ---------------------------------------------------------------------------
#define GT_K 16
#define A_LEN 264                       // dup A k-row: 256 + 8 pad
#define B_LEN 132
#define STG_FL (GT_K * A_LEN + GT_K * B_LEN)   // 6336 floats
#define SG_SMEM (2 * STG_FL * 4)               // 50688 B

__global__ __launch_bounds__(256, 2) void sgemm_sim(float* __restrict__ out) {
    extern __shared__ float sm[];

    const int tid  = threadIdx.x;
    const int wid  = tid >> 5;
    const int lane = tid & 31;
    const int wr   = wid & 3;           // 4 warp-rows of 32
    const int wc   = wid >> 2;          // 2 warp-cols of 64
    const int lr   = lane & 3;          // 4 lane-rows of 8
    const int lc   = lane >> 2;         // 8 lane-cols of 8
    const int r0   = wr * 32 + lr * 8;
    const int c0   = wc * 64 + lc * 8;

    const int bb = blockIdx.z;
    const int m0 = blockIdx.y * 128;
    const int n0 = blockIdx.x * 128;

    const float4* Af4 = (const float4*)(g_f1n + ((size_t)(bb * N_ + m0)) * D_);
    const float4* Bf4 = (const float4*)(g_f2n + ((size_t)(bb * N_ + n0)) * D_);

    const int r_a = tid >> 2;           // 0..63 (second chunk +64)
    const int kq  = tid & 3;

    float4 pa0, pa1, pb0, pb1;

#define LOAD_STAGE(kc)                                                   \
    do {                                                                 \
        pa0 = Af4[(size_t)r_a * 64 + (kc) * 4 + kq];                     \
        pa1 = Af4[(size_t)(r_a + 64) * 64 + (kc) * 4 + kq];              \
        pb0 = Bf4[(size_t)r_a * 64 + (kc) * 4 + kq];                     \
        pb1 = Bf4[(size_t)(r_a + 64) * 64 + (kc) * 4 + kq];              \
    } while (0)

#define STORE_STAGE(buf)                                                 \
    do {                                                                 \
        float* As = sm + (buf) * STG_FL;                                 \
        float* Bs = As + GT_K * A_LEN;                                   \
        const float va0[4] = {pa0.x, pa0.y, pa0.z, pa0.w};               \
        const float va1[4] = {pa1.x, pa1.y, pa1.z, pa1.w};               \
        const float vb0[4] = {pb0.x, pb0.y, pb0.z, pb0.w};               \
        const float vb1[4] = {pb1.x, pb1.y, pb1.z, pb1.w};               \
        _Pragma("unroll")                                                \
        for (int e = 0; e < 4; e++) {                                    \
            *(float2*)(As + (kq * 4 + e) * A_LEN + 2 * r_a) =            \
                make_float2(va0[e], va0[e]);                             \
            *(float2*)(As + (kq * 4 + e) * A_LEN + 2 * (r_a + 64)) =     \
                make_float2(va1[e], va1[e]);                             \
            Bs[(kq * 4 + e) * B_LEN + r_a] = vb0[e];                     \
            Bs[(kq * 4 + e) * B_LEN + r_a + 64] = vb1[e];                \
        }                                                                \
    } while (0)

    unsigned long long c[8][4];
#pragma unroll
    for (int i = 0; i < 8; i++)
#pragma unroll
        for (int j = 0; j < 4; j++) c[i][j] = 0ull;

    LOAD_STAGE(0);
    STORE_STAGE(0);
    __syncthreads();

#pragma unroll 1
    for (int kc = 0; kc < 16; ++kc) {
        if (kc + 1 < 16) LOAD_STAGE(kc + 1);

        const float* As = sm + (kc & 1) * STG_FL;
        const float* Bs = As + GT_K * A_LEN;
#pragma unroll
        for (int k = 0; k < GT_K; ++k) {
            ulonglong2 A01 = *(const ulonglong2*)(As + k * A_LEN + 2 * r0);
            ulonglong2 A23 = *(const ulonglong2*)(As + k * A_LEN + 2 * r0 + 4);
            ulonglong2 A45 = *(const ulonglong2*)(As + k * A_LEN + 2 * r0 + 8);
            ulonglong2 A67 = *(const ulonglong2*)(As + k * A_LEN + 2 * r0 + 12);
            ulonglong2 B01 = *(const ulonglong2*)(Bs + k * B_LEN + c0);
            ulonglong2 B23 = *(const ulonglong2*)(Bs + k * B_LEN + c0 + 4);
            unsigned long long a[8] = {A01.x, A01.y, A23.x, A23.y,
                                       A45.x, A45.y, A67.x, A67.y};
            unsigned long long b[4] = {B01.x, B01.y, B23.x, B23.y};
#pragma unroll
            for (int i = 0; i < 8; i++)
#pragma unroll
                for (int j = 0; j < 4; j++)
                    c[i][j] = ffma2(a[i], b[j], c[i][j]);
        }

        if (kc + 1 < 16) {
            STORE_STAGE((kc + 1) & 1);
            __syncthreads();
        }
    }

    // epilogue: direct store
#pragma unroll
    for (int i = 0; i < 8; i++) {
        float* op = out + ((size_t)(bb * N_ + m0 + r0 + i)) * N_ + n0 + c0;
        *(ulonglong2*)op = make_ulonglong2(c[i][0], c[i][1]);
        *(ulonglong2*)(op + 4) = make_ulonglong2(c[i][2], c[i][3]);
    }
#undef LOAD_STAGE
#undef STORE_STAGE
}

// ---------------------------------------------------------------------------
__device__ __forceinline__ void insert_cand(float* tv, int* ti, float v, int idx) {
    int pos = NC - 1;
    while (pos > 0 && tv[pos - 1] < v) {
        tv[pos] = tv[pos - 1];
        ti[pos] = ti[pos - 1];
        pos--;
    }
    tv[pos] = v;
    ti[pos] = idx;
}
__device__ __forceinline__ void insert_final(float* tv, int* ti, float v, int idx) {
    int pos = K_ - 1;
    while (pos > 0 && (tv[pos - 1] < v || (tv[pos - 1] == v && ti[pos - 1] > idx))) {
        tv[pos] = tv[pos - 1];
        ti[pos] = ti[pos - 1];
        pos--;
    }
    tv[pos] = v;
    ti[pos] = idx;
}

// ---------------------------------------------------------------------------
// K3: candidate select — 4 threads/row (lane-interleaved, coalesced),
// exact per-quarter top-40 + exact 4-way merge -> g_cv/g_ci
// block 256 -> 64 rows; grid 256
// ---------------------------------------------------------------------------
#define SEL_SMEM (256 * NC * 8)   // 81920 B

__global__ __launch_bounds__(256) void select_cand(const float* __restrict__ sim) {
    extern __shared__ float sms[];
    float* sv = sms;
    int*   si = (int*)(sms + 256 * NC);

    const int tid  = threadIdx.x;
    const int rl   = tid >> 2;
    const int q    = tid & 3;
    const int grow = blockIdx.x * 64 + rl;

    float* tv = sv + tid * NC;
    int*   ti = si + tid * NC;
#pragma unroll
    for (int k = 0; k < NC; k++) { tv[k] = -3.4e38f; ti[k] = 0; }

    const float4* p = (const float4*)(sim + (size_t)grow * N_);
    float tmin = -3.4e38f;

    for (int it = 0; it < 64; ++it) {
        float4 x0 = p[(it * 4 + 0) * 4 + q];
        float4 x1 = p[(it * 4 + 1) * 4 + q];
        float4 x2 = p[(it * 4 + 2) * 4 + q];
        float4 x3 = p[(it * 4 + 3) * 4 + q];
        float mx = fmaxf(fmaxf(fmaxf(x0.x, x0.y), fmaxf(x0.z, x0.w)),
                  fmaxf(fmaxf(fmaxf(x1.x, x1.y), fmaxf(x1.z, x1.w)),
                  fmaxf(fmaxf(fmaxf(x2.x, x2.y), fmaxf(x2.z, x2.w)),
                        fmaxf(fmaxf(x3.x, x3.y), fmaxf(x3.z, x3.w)))));
        if (mx > tmin) {
            const float vals[16] = {x0.x, x0.y, x0.z, x0.w, x1.x, x1.y, x1.z, x1.w,
                                    x2.x, x2.y, x2.z, x2.w, x3.x, x3.y, x3.z, x3.w};
#pragma unroll
            for (int s = 0; s < 4; s++)
#pragma unroll
                for (int e = 0; e < 4; e++) {
                    float v = vals[s * 4 + e];
                    if (v > tmin) {
                        insert_cand(tv, ti, v, it * 64 + s * 16 + q * 4 + e);
                        tmin = tv[NC - 1];
                    }
                }
        }
    }
    __syncthreads();

    // exact 4-way merge (tie -> lowest quarter list)
    if (tid < 64) {
        int h[4] = {0, 0, 0, 0};
        float* ov = g_cv + (size_t)(blockIdx.x * 64 + tid) * NC;
        int*   oi = g_ci + (size_t)(blockIdx.x * 64 + tid) * NC;
#pragma unroll 1
        for (int k = 0; k < NC; k++) {
            float best = -3.4e38f;
            int bq = 0;
#pragma unroll
            for (int qq = 0; qq < 4; qq++) {
                float v = sv[(tid * 4 + qq) * NC + h[qq]];
                if (v > best) { best = v; bq = qq; }
            }
            ov[k] = best;
            oi[k] = si[(tid * 4 + bq) * NC + h[bq]];
            h[bq]++;
        }
    }
}

// ---------------------------------------------------------------------------
// K4: finalize — 4 rows/block, 4 warps/row x 10 cands (proven warp-tree dot),
// stable top-32 + softmax + zero rows + scatter
// ---------------------------------------------------------------------------
__global__ __launch_bounds__(512) void finalize(float* __restrict__ out) {
    __shared__ float sv4[4][NC];
    __shared__ int   si4[4][NC];
    __shared__ float swt[4][K_];
    __shared__ int   sfi[4][K_];

    const int tid  = threadIdx.x;
    const int wid  = tid >> 5;
    const int lane = tid & 31;
    const int rloc = wid >> 2;
    const int sw   = wid & 3;
    const int grow = blockIdx.x * 4 + rloc;
    const int bb   = grow >> 12;

    int myc = 0;
    if (lane < 10) {
        myc = g_ci[(size_t)grow * NC + sw * 10 + lane];
        si4[rloc][sw * 10 + lane] = myc;
    }

    const float4* a4 = (const float4*)(g_f1n + (size_t)grow * D_);
    float4 a0 = a4[lane], a1 = a4[lane + 32];
    const float* f2b = g_f2n + ((size_t)bb << 12) * D_;

#pragma unroll 2
    for (int cdx = 0; cdx < 10; ++cdx) {
        int col = __shfl_sync(0xffffffffu, myc, cdx);
        const float4* b4 = (const float4*)(f2b + (size_t)col * D_);
        float4 b0 = b4[lane], b1 = b4[lane + 32];
        float sv = a0.x * b0.x;
        sv = fmaf(a0.y, b0.y, sv);
        sv = fmaf(a0.z, b0.z, sv);
        sv = fmaf(a0.w, b0.w, sv);
        sv = fmaf(a1.x, b1.x, sv);
        sv = fmaf(a1.y, b1.y, sv);
        sv = fmaf(a1.z, b1.z, sv);
        sv = fmaf(a1.w, b1.w, sv);
#pragma unroll
        for (int o = 16; o; o >>= 1) sv += __shfl_xor_sync(0xffffffffu, sv, o);
        if (lane == 0) sv4[rloc][sw * 10 + cdx] = sv;
    }
    __syncthreads();

    if (tid < 4) {
        float fv[K_];
        int fi[K_];
#pragma unroll
        for (int k = 0; k < K_; k++) { fv[k] = -3.4e38f; fi[k] = 0x7fffffff; }
#pragma unroll
        for (int cdx = 0; cdx < NC; cdx++) {
            float v = sv4[tid][cdx];
            int idx = si4[tid][cdx];
            if (v > fv[K_ - 1] || (v == fv[K_ - 1] && idx < fi[K_ - 1]))
                insert_final(fv, fi, v, idx);
        }
        float mx = fv[0];
        float e[K_];
        float ssum = 0.0f;
#pragma unroll
        for (int k = 0; k < K_; k++) { e[k] = expf((fv[k] - mx) * INV_T); ssum += e[k]; }
        float inv = 1.0f / ssum;
#pragma unroll
        for (int k = 0; k < K_; k++) { swt[tid][k] = e[k] * inv; sfi[tid][k] = fi[k]; }
    }
    __syncthreads();

    // zero the 4 sim rows (replaces global memset)
    {
        const int rz = tid >> 7;
        const int pz = tid & 127;
        float4* rowp = (float4*)(out + (size_t)(blockIdx.x * 4 + rz) * N_);
        const float4 z = make_float4(0.f, 0.f, 0.f, 0.f);
#pragma unroll
        for (int j = 0; j < 8; j++) rowp[pz + j * 128] = z;
    }
    __syncthreads();

    if (tid < 128) {
        const int rl = tid >> 5;
        const int k  = lane;
        const int g2 = blockIdx.x * 4 + rl;
        out[(size_t)g2 * N_ + sfi[rl][k]] = swt[rl][k];
        out[(size_t)B_ * N_ * N_ + (size_t)g2 * K_ + k] = (float)sfi[rl][k];
    }
}

// ---------------------------------------------------------------------------
extern "C" void kernel_launch(void* const* d_in, const int* in_sizes, int n_in,
                              void* d_out, int out_size) {
    const float* F1 = (const float*)d_in[0];
    const float* F2 = (const float*)d_in[1];
    float* out = (float*)d_out;

    normalize_kernel<<<4096, 256>>>(F1, F2);

    cudaFuncSetAttribute(sgemm_sim,
                         cudaFuncAttributeMaxDynamicSharedMemorySize, SG_SMEM);
    sgemm_sim<<<dim3(N_ / 128, N_ / 128, B_), 256, SG_SMEM>>>(out);

    cudaFuncSetAttribute(select_cand,
                         cudaFuncAttributeMaxDynamicSharedMemorySize, SEL_SMEM);
    select_cand<<<(B_ * N_) / 64, 256, SEL_SMEM>>>(out);

    finalize<<<(B_ * N_) / 4, 512>>>(out);
}